// round 14
// baseline (speedup 1.0000x reference)
#include <cuda_runtime.h>
#include <math.h>

#define NTH  256
#define BM   64
#define AEMB 16
#define DIN  480

// ---- shared memory layout (float offsets) ----
#define X0P  132
#define ASP  17
#define AS_OFF  (BM * X0P)               // 8448
#define B1_OFF  (AS_OFF + BM * ASP)      // 9536
#define B2_OFF  (B1_OFF + 128)           // 9664
#define WB_OFF  (B2_OFF + 16)            // 9680 (byte 38720, 16B aligned)
#define SLOT_U32 4096                    // 16KB per ring slot
#define MID_OFF (WB_OFF + 3 * SLOT_U32)  // 21968
#define SMEM_FLOATS (MID_OFF + BM * 17)  // 23056
#define SMEM_BYTES  (SMEM_FLOATS * 4)    // 92224 -> 2 CTAs/SM

typedef unsigned long long ull;

// Pre-packed weights (fp16 pairs in MMA fragment order)
// W1p: [i(128)][tile(16)][lane(32)][h(2)] = 131072 u32 (chunk of 4 i = 4096 u32)
// W2p: [i(128)][tile(2)][lane(32)][h(2)]  = 16384 u32  (chunk of 16 i = 2048 u32)
__device__ unsigned g_W1p[131072];
__device__ unsigned g_W2p[16384];

__device__ __forceinline__ unsigned pkh2(float lo, float hi) {
    unsigned d;
    asm("cvt.rn.f16x2.f32 %0, %2, %1;" : "=r"(d) : "f"(lo), "f"(hi));
    return d;
}
__device__ __forceinline__ void mma16(float* d, unsigned a0, unsigned a1,
                                      unsigned a2, unsigned a3,
                                      unsigned b0, unsigned b1) {
    asm volatile(
        "mma.sync.aligned.m16n8k16.row.col.f32.f16.f16.f32 "
        "{%0,%1,%2,%3}, {%4,%5,%6,%7}, {%8,%9}, {%0,%1,%2,%3};"
        : "+f"(d[0]), "+f"(d[1]), "+f"(d[2]), "+f"(d[3])
        : "r"(a0), "r"(a1), "r"(a2), "r"(a3), "r"(b0), "r"(b1));
}
__device__ __forceinline__ void cpa16(unsigned s, const void* g) {
    asm volatile(
        "{ .reg .u64 ga; cvta.to.global.u64 ga, %1;"
        "  cp.async.cg.shared.global [%0], [ga], 16; }"
        :: "r"(s), "l"(g) : "memory");
}
#define CPA_COMMIT() asm volatile("cp.async.commit_group;" ::: "memory")
#define CPA_WAIT1()  asm volatile("cp.async.wait_group 1;" ::: "memory")
#define CPA_WAIT0()  asm volatile("cp.async.wait_group 0;" ::: "memory")
__device__ __forceinline__ unsigned smem_u32(const void* p) {
    unsigned a;
    asm("{ .reg .u64 t; cvta.to.shared.u64 t, %1; cvt.u32.u64 %0, t; }" : "=r"(a) : "l"(p));
    return a;
}
__device__ __forceinline__ float silu_f(float x) { return x / (1.0f + __expf(-x)); }

// ---------------- pre-pack kernel (layouts unchanged) ----------------
__global__ void __launch_bounds__(256, 4)
pack_kernel(const float* __restrict__ W1, const float* __restrict__ W2) {
    int tid = blockIdx.x * 256 + threadIdx.x;
    if (tid < 131072) {
        int h = tid & 1, ll = (tid >> 1) & 31, t = (tid >> 6) & 15, i = tid >> 10;
        int q = ll >> 2, mk = ll & 3;
        int n = t * 8 + q, kr = h * 8 + 2 * mk;
        const float* p = W1 + ((size_t)(i * 16 + kr)) * 224 + n;
        g_W1p[tid] = pkh2(p[0], p[224]);
    } else {
        int t2 = tid - 131072;
        if (t2 < 16384) {
            int h = t2 & 1, ll = (t2 >> 1) & 31, tt = (t2 >> 6) & 1, i = t2 >> 7;
            int q = ll >> 2, mk = ll & 3;
            int n = tt * 8 + q, kr = h * 8 + 2 * mk;
            const float* p = W2 + ((size_t)(i * 16 + kr)) * 16 + n;
            g_W2p[t2] = pkh2(p[0], p[16]);
        }
    }
}

// issue copies for unified chunk c (0..31 = W1 4-i chunks, 32..39 = W2 16-i chunks)
__device__ __forceinline__ void issue_chunk(int c, unsigned wbB, int tid) {
    if (c < 32) {
        const unsigned* src = g_W1p + c * 4096 + tid * 4;
        unsigned d = wbB + (c % 3) * 16384 + tid * 16;
        cpa16(d,         src);
        cpa16(d + 4096,  src + 1024);
        cpa16(d + 8192,  src + 2048);
        cpa16(d + 12288, src + 3072);
    } else if (c < 40) {
        const unsigned* src = g_W2p + (c - 32) * 2048 + tid * 4;
        unsigned d = wbB + (c % 3) * 16384 + tid * 16;
        cpa16(d,        src);
        cpa16(d + 4096, src + 1024);
    }
}

// ---------------- main kernel ----------------
__global__ void __launch_bounds__(NTH, 2)
tp_head_kernel(const float* __restrict__ nv, const float* __restrict__ ae,
               const float* __restrict__ b1, const float* __restrict__ b2,
               const float* __restrict__ W3, const float* __restrict__ b3,
               const float* __restrict__ W4, const float* __restrict__ b4,
               float* __restrict__ out)
{
    extern __shared__ float sm[];
    float*    x0s  = sm;                        // [64][132] x0, later scalars
    float*    as_  = sm + AS_OFF;               // [64][17]
    float*    b1s  = sm + B1_OFF;
    float*    b2s  = sm + B2_OFF;
    unsigned* wb32 = (unsigned*)(sm + WB_OFF);  // 3 ring slots x 4096 u32
    float*    wbf  = sm + WB_OFF;               // float view (phase 3)
    float*    mids = sm + MID_OFF;              // [64][17]

    const int tid = threadIdx.x;
    const int wid = tid >> 5;
    const int l   = tid & 31;
    const int n0  = blockIdx.x * BM;
    const int q   = l >> 2;
    const int mk  = l & 3;

    const unsigned wbB = smem_u32(wb32);

    // ---- prologue: issue chunks 0,1; stage x0, a, b1, b2 ----
    issue_chunk(0, wbB, tid); CPA_COMMIT();
    issue_chunk(1, wbB, tid); CPA_COMMIT();

    for (int t = tid; t < BM * 32; t += NTH) {
        int lr = t >> 5, c4 = (t & 31) << 2;
        float4 v = *(const float4*)(nv + (size_t)(n0 + lr) * DIN + c4);
        *(float4*)(x0s + lr * X0P + c4) = v;
    }
    if (tid < BM * 4) {
        int lr = tid >> 2, c4 = (tid & 3) << 2;
        float4 v = *(const float4*)(ae + (size_t)(n0 + lr) * AEMB + c4);
        float* dst = as_ + lr * ASP + c4;
        dst[0] = v.x; dst[1] = v.y; dst[2] = v.z; dst[3] = v.w;
    }
    if (tid < 128) b1s[tid] = b1[tid];
    if (tid >= 128 && tid < 144) b2s[tid - 128] = b2[tid - 128];

    // ---- MMA geometry: warp = 16 rows (rs) x 64 cols (cg) ----
    const int rs = wid >> 1;
    const int cg = wid & 1;
    float ar[2][4];
    {
        // a values needed after first sync; load from global directly (pre-sync safe)
        int r0g = n0 + rs * 16 + q, r1g = r0g + 8;
        ar[0][0] = ae[r0g * AEMB + 2 * mk];     ar[0][1] = ae[r0g * AEMB + 2 * mk + 1];
        ar[0][2] = ae[r0g * AEMB + 2 * mk + 8]; ar[0][3] = ae[r0g * AEMB + 2 * mk + 9];
        ar[1][0] = ae[r1g * AEMB + 2 * mk];     ar[1][1] = ae[r1g * AEMB + 2 * mk + 1];
        ar[1][2] = ae[r1g * AEMB + 2 * mk + 8]; ar[1][3] = ae[r1g * AEMB + 2 * mk + 9];
    }
    float acc[8][4];
#pragma unroll
    for (int t = 0; t < 8; ++t)
#pragma unroll
        for (int e = 0; e < 4; ++e) acc[t][e] = 0.0f;

    // =============== Phase 1: 32 chunks of 4 i ===============
    for (int sc = 0; sc < 32; ++sc) {
        CPA_WAIT1();
        __syncthreads();

        const unsigned* bb = wb32 + (sc % 3) * SLOT_U32;
        float4 va = *(const float4*)(x0s + (rs * 16 + q) * X0P + sc * 4);
        float4 vb = *(const float4*)(x0s + (rs * 16 + 8 + q) * X0P + sc * 4);
        float xa[4] = {va.x, va.y, va.z, va.w};
        float xb[4] = {vb.x, vb.y, vb.z, vb.w};
#pragma unroll
        for (int il = 0; il < 4; ++il) {
            unsigned A0 = pkh2(xa[il] * ar[0][0], xa[il] * ar[0][1]);
            unsigned A1 = pkh2(xb[il] * ar[1][0], xb[il] * ar[1][1]);
            unsigned A2 = pkh2(xa[il] * ar[0][2], xa[il] * ar[0][3]);
            unsigned A3 = pkh2(xb[il] * ar[1][2], xb[il] * ar[1][3]);
            const ull* bp = (const ull*)bb + (il * 16 + cg * 8) * 32 + l;
#pragma unroll
            for (int t = 0; t < 8; ++t) {
                ull bv = bp[t * 32];
                unsigned bx0, bx1;
                asm("mov.b64 {%0,%1}, %2;" : "=r"(bx0), "=r"(bx1) : "l"(bv));
                mma16(acc[t], A0, A1, A2, A3, bx0, bx1);
            }
        }
        issue_chunk(sc + 2, wbB, tid);   // chunks 2..33 (32,33 = W2 c0,c1)
        CPA_COMMIT();
    }

    // ---- epilogue 1: scalars = silu(s*INV + b1) -> x0s ----
    __syncthreads();   // all phase-1 reads of x0s done
    const float INV = 0.022097086912079608f;   // 1/sqrt(128*16)
#pragma unroll
    for (int t = 0; t < 8; ++t) {
        int c0 = cg * 64 + t * 8 + mk * 2;
        int row = rs * 16 + q;
        float* a = acc[t];
        x0s[row * X0P + c0]           = silu_f(a[0] * INV + b1s[c0]);
        x0s[row * X0P + c0 + 1]       = silu_f(a[1] * INV + b1s[c0 + 1]);
        x0s[(row + 8) * X0P + c0]     = silu_f(a[2] * INV + b1s[c0]);
        x0s[(row + 8) * X0P + c0 + 1] = silu_f(a[3] * INV + b1s[c0 + 1]);
    }

    // ---- phase-2: warp = same 16 rows (sW==rs) x 8 cols (th==cg) ----
    const int th = cg;
    float acc2[4] = {0.0f, 0.0f, 0.0f, 0.0f};

    // =============== Phase 2: 8 chunks of 16 i (unified chunks 32..39) ===============
    for (int cN = 0; cN < 8; ++cN) {
        if (cN == 7) { CPA_WAIT0(); } else { CPA_WAIT1(); }
        __syncthreads();

        const unsigned* bb = wb32 + ((cN + 32) % 3) * SLOT_U32;
#pragma unroll
        for (int ib = 0; ib < 4; ++ib) {
            float4 v0 = *(const float4*)(x0s + (rs * 16 + q) * X0P + cN * 16 + ib * 4);
            float4 v1 = *(const float4*)(x0s + (rs * 16 + 8 + q) * X0P + cN * 16 + ib * 4);
            float xr0[4] = {v0.x, v0.y, v0.z, v0.w};
            float xr1[4] = {v1.x, v1.y, v1.z, v1.w};
#pragma unroll
            for (int i4 = 0; i4 < 4; ++i4) {
                int il = ib * 4 + i4;
                float s0 = xr0[i4], s1 = xr1[i4];
                unsigned a0 = pkh2(s0 * ar[0][0], s0 * ar[0][1]);
                unsigned a1 = pkh2(s1 * ar[1][0], s1 * ar[1][1]);
                unsigned a2 = pkh2(s0 * ar[0][2], s0 * ar[0][3]);
                unsigned a3 = pkh2(s1 * ar[1][2], s1 * ar[1][3]);
                ull bv = ((const ull*)bb)[(il * 2 + th) * 32 + l];
                unsigned bx0, bx1;
                asm("mov.b64 {%0,%1}, %2;" : "=r"(bx0), "=r"(bx1) : "l"(bv));
                mma16(acc2, a0, a1, a2, a3, bx0, bx1);
            }
        }
        issue_chunk(cN + 34, wbB, tid);  // no-op for >=40
        CPA_COMMIT();
    }

    // ---- epilogue 2 ----
    {
        int c0 = th * 8 + mk * 2;
        int row = rs * 16 + q;
        mids[row * 17 + c0]           = acc2[0] * INV + b2s[c0];
        mids[row * 17 + c0 + 1]       = acc2[1] * INV + b2s[c0 + 1];
        mids[(row + 8) * 17 + c0]     = acc2[2] * INV + b2s[c0];
        mids[(row + 8) * 17 + c0 + 1] = acc2[3] * INV + b2s[c0 + 1];
    }
    __syncthreads();

    // stage W3/W4/b3/b4 into wbf (ring slots dead now)
    if (tid < 256) wbf[tid] = W3[tid];
    if (tid < 16)  { wbf[256 + tid] = W4[tid]; wbf[288 + tid] = b3[tid]; }
    if (tid == 0)  wbf[304] = b4[0];
    __syncthreads();

    // =============== Phase 3: tiny 16x16 head ===============
    if (tid < BM) {
        float mv[16];
#pragma unroll
        for (int j = 0; j < 16; ++j) mv[j] = mids[tid * 17 + j];
        float o = 0.0f;
#pragma unroll
        for (int jo = 0; jo < 16; ++jo) {
            float t = 0.0f;
#pragma unroll
            for (int ji = 0; ji < 16; ++ji) t += mv[ji] * wbf[ji * 16 + jo];
            t = t * 0.25f + wbf[288 + jo];
            o += silu_f(t) * wbf[256 + jo];
        }
        out[n0 + tid] = o * 0.25f + wbf[304];
    }
}

extern "C" void kernel_launch(void* const* d_in, const int* in_sizes, int n_in,
                              void* d_out, int out_size) {
    const float* nv = (const float*)d_in[0];
    const float* ae = (const float*)d_in[1];
    const float* W1 = (const float*)d_in[2];
    // d_in[3], d_in[4] dead (W1_l1, W1_l2)
    const float* b1 = (const float*)d_in[5];
    const float* W2 = (const float*)d_in[6];
    const float* b2 = (const float*)d_in[7];
    const float* W3 = (const float*)d_in[8];
    const float* b3 = (const float*)d_in[9];
    const float* W4 = (const float*)d_in[10];
    const float* b4 = (const float*)d_in[11];
    float* out = (float*)d_out;

    int nodes = in_sizes[1] / AEMB;
    int grid  = nodes / BM;

    pack_kernel<<<576, 256>>>(W1, W2);

    cudaFuncSetAttribute(tp_head_kernel,
                         cudaFuncAttributeMaxDynamicSharedMemorySize, SMEM_BYTES);
    tp_head_kernel<<<grid, NTH, SMEM_BYTES>>>(nv, ae, b1, b2,
                                              W3, b3, W4, b4, out);
}